// round 12
// baseline (speedup 1.0000x reference)
#include <cuda_runtime.h>

// CTC forward scan, linear domain, x4-factored:
//   G_j(t+1) = W_t[s_j]*G_{j-1}(t) + G_j(t),  W_t[s] = exp(x[t,s]-x[t,4])
//   fwd[j] = log(G) + e*ln2 + sum_t x4
//
// R9: TWO WARPS PER BATCH (64 lanes x PB=8 positions), halo via shfl inside
// each warp + one parity-buffered smem slot across the warp boundary, one
// named bar.sync(64) per KB=8 steps. Convert/prefetch of the W pair-table is
// split across both warps (16 taus each) so no single warp carries a MUFU/STS
// spike into the barrier. Pair-row pointers are hoisted per chunk and bumped
// by += KB per region so every ladder LDS.64 has an immediate offset.
// Scaling identical to R7 (proven): per-lane pow2 exponent, pre-renorm halo
// with packed (e,ex,hasmass), common-scale mixing with factors <= 1.

#define XCH  32
#define KB   8
#define PB   8
#define NU   15              // PB + KB - 1 updates per step
#define NP   8               // pair rows per step (last single, padded)
#define PSTR 33              // float2 per table row: conflict-free
#define NREG (XCH / KB)      // 4 regions per chunk (even -> parity alternates)
#define TPB  128

#define BBAR() asm volatile("bar.sync %0, %1;" :: "r"(batch + 1), "n"(64) : "memory")

__device__ __forceinline__ float exp2i_le(int d) {
    int b = d + 127;
    b = b < 0 ? 0 : (b > 254 ? 254 : b);
    return __int_as_float(b << 23);
}

__global__ __launch_bounds__(TPB, 1)
void ctc_fwd(const float* __restrict__ x,
             const int*   __restrict__ seqs,
             const int*   __restrict__ seqlens,
             float*       __restrict__ out,
             int nt, int nb, int ns)
{
    __shared__ float2 shP [2][2][16 * PSTR];  // [batch][buf][row*PSTR+tau]
    __shared__ float4 bndA[2][2], bndB[2][2]; // [batch][parity] boundary G
    __shared__ int    bndP[2][2];             // boundary pack
    __shared__ float  gall[2][512];
    __shared__ int    eall[2][64];
    __shared__ double dsum[2][2];

    const int  tid   = threadIdx.x;
    const int  batch = tid >> 6;          // 0/1 within CTA
    const int  w     = (tid >> 5) & 1;    // warp within batch
    const int  l     = tid & 31;
    const int  L     = tid & 63;          // lane within batch
    const int  bb    = blockIdx.x * 2 + batch;
    const bool bv    = (bb < nb);
    const int  sl    = bv ? seqlens[bb] : 0;
    const int  jmin  = L * PB;

    // move indices: update i writes G[i+1] (position jmin+i-7), uses
    // seqs[jmin+i-8], i = 0..14
    int s[NU + 1];
    #pragma unroll
    for (int k = 0; k < NU; ++k) {
        int q = jmin + k - KB;
        s[k] = (bv && q >= 0 && q < ns) ? seqs[(long long)bb * ns + q] : 0;
    }
    s[NU] = s[NU - 1];
    int pq[NP];
    #pragma unroll
    for (int q = 0; q < NP; ++q)
        pq[q] = (s[2 * q] * 4 + s[2 * q + 1]) * PSTR;

    float G[KB + PB];
    #pragma unroll
    for (int i = 0; i < KB + PB; ++i) G[i] = 0.0f;
    if (L == 0 && bv) G[KB] = 1.0f;       // position 0: fwd=0 -> G=1
    int e = 0;

    // ---- W loader: both warps, lanes 0..15, tau = w*16 + l ----
    const bool  ldr = (l < 16) && bv;
    const int   tau = w * 16 + l;
    float a0 = 0.f, a1 = 0.f, a2 = 0.f, a3 = 0.f, a4 = 0.f;
    double x4s = 0.0;

    auto prefetch = [&](int c) {          // LDG only into registers
        if (ldr) {
            int tt = c * XCH + tau;
            if (tt < nt) {
                const float* xp = x + ((long long)tt * nb + bb) * 5;
                a0 = xp[0]; a1 = xp[1]; a2 = xp[2]; a3 = xp[3]; a4 = xp[4];
            } else {
                a0 = a1 = a2 = a3 = -1e9f;   // exp->0: freeze G past nt
                a4 = 0.f;
            }
        }
    };
    auto convert = [&](int c) {           // expf + 16 STS.64 pair rows
        if (ldr) {
            float wv[4];
            wv[0] = __expf(a0 - a4); wv[1] = __expf(a1 - a4);
            wv[2] = __expf(a2 - a4); wv[3] = __expf(a3 - a4);
            float2* row = &shP[batch][c & 1][tau];
            #pragma unroll
            for (int aa = 0; aa < 4; ++aa)
                #pragma unroll
                for (int bq = 0; bq < 4; ++bq)
                    row[(aa * 4 + bq) * PSTR] = make_float2(wv[aa], wv[bq]);
            if (c * XCH + tau < nt) x4s += (double)a4;
        }
    };

    prefetch(0); convert(0); prefetch(1);

    // initial pack (post-"region -1" state) + boundary slot parity 0
    float mx = G[KB];
    #pragma unroll
    for (int i = KB + 1; i < KB + PB; ++i) mx = fmaxf(mx, G[i]);
    int ex = (__float_as_int(mx) >> 23) - 127;
    int hm = (mx > 0.0f) ? 1 : 0;
    int pack = (e << 9) | ((ex + 128) << 1) | hm;
    if (w == 0 && l == 31) {
        bndA[batch][0] = make_float4(G[8],  G[9],  G[10], G[11]);
        bndB[batch][0] = make_float4(G[12], G[13], G[14], G[15]);
        bndP[batch][0] = pack;
    }

    const int NC = (nt + XCH - 1) / XCH;
    for (int c = 0; c < NC; ++c) {
        // hoist pair-row pointers for this chunk (immediate offsets below)
        const float2* rp[NP];
        {
            const float2* cbb = &shP[batch][c & 1][0];
            #pragma unroll
            for (int q = 0; q < NP; ++q) rp[q] = cbb + pq[q];
        }
        #pragma unroll 1
        for (int r = 0; r < NREG; ++r) {
            const int par = r & 1;
            BBAR();   // prev-region boundary STS visible; WAR on parity slots

            // ---- exchange: shfl halo, smem at the warp boundary ----
            int packL = __shfl_up_sync(0xffffffffu, pack, 1);
            float h[KB];
            #pragma unroll
            for (int i = 0; i < KB; ++i)
                h[i] = __shfl_up_sync(0xffffffffu, G[KB + i], 1);
            if (l == 0) {
                if (w == 1) {
                    float4 A = bndA[batch][par], B = bndB[batch][par];
                    packL = bndP[batch][par];
                    h[0] = A.x; h[1] = A.y; h[2] = A.z; h[3] = A.w;
                    h[4] = B.x; h[5] = B.y; h[6] = B.z; h[7] = B.w;
                } else {
                    packL = 0;                 // no left neighbor
                }
            }

            // ---- mix at common scale (factors <= 1, no overflow) ----
            int hL  = packL & 1;
            int exL = ((packL >> 1) & 255) - 128;
            int eL  = packL >> 9;
            const int NEG = -(1 << 29);
            int EO = hm ? (e + ex)   : NEG;
            int EL = hL ? (eL + exL) : NEG;
            int cc = EO > EL ? EO : EL;
            if (cc == NEG) cc = 0;
            float rs = exp2i_le(e - cc);
            float rl = hL ? exp2i_le(eL - cc) : 0.0f;
            #pragma unroll
            for (int i = 0; i < KB; ++i) G[i] = h[i] * rl;
            #pragma unroll
            for (int i = KB; i < KB + PB; ++i) G[i] *= rs;
            e = cc;

            // ---- ladder: KB steps, double-buffered pair loads ----
            float2 W0[NP], W1[NP];
            #pragma unroll
            for (int q = 0; q < NP; ++q) W0[q] = rp[q][0];
            #pragma unroll
            for (int k = 0; k < KB; ++k) {
                float2* cur = (k & 1) ? W1 : W0;
                float2* nxt = (k & 1) ? W0 : W1;
                if (k < KB - 1) {
                    #pragma unroll
                    for (int q = 0; q < NP; ++q) nxt[q] = rp[q][k + 1];
                }
                // in-place, strictly descending targets
                G[NU] = fmaf(cur[NP - 1].x, G[NU - 1], G[NU]);
                #pragma unroll
                for (int q = NP - 2; q >= 0; --q) {
                    G[2*q + 2] = fmaf(cur[q].y, G[2*q + 1], G[2*q + 2]);
                    G[2*q + 1] = fmaf(cur[q].x, G[2*q],     G[2*q + 1]);
                }
            }
            #pragma unroll
            for (int q = 0; q < NP; ++q) rp[q] += KB;

            // ---- post: pack state; publish warp-boundary slot ----
            mx = G[KB];
            #pragma unroll
            for (int i = KB + 1; i < KB + PB; ++i) mx = fmaxf(mx, G[i]);
            ex = (__float_as_int(mx) >> 23) - 127;
            hm = (mx > 0.0f) ? 1 : 0;
            pack = (e << 9) | ((ex + 128) << 1) | hm;
            if (w == 0 && l == 31) {
                bndA[batch][par ^ 1] = make_float4(G[8],  G[9],  G[10], G[11]);
                bndB[batch][par ^ 1] = make_float4(G[12], G[13], G[14], G[15]);
                bndP[batch][par ^ 1] = pack;
            }
        }
        convert(c + 1);       // regs from prefetch(c+1); bar at next region
        prefetch(c + 2);      // covers visibility before first use
    }

    // ---- epilogue ----
    BBAR();
    #pragma unroll
    for (int i = 0; i < PB; ++i) gall[batch][jmin + i] = G[KB + i];
    eall[batch][L] = e;
    {
        double v = x4s;
        #pragma unroll
        for (int o = 16; o; o >>= 1)
            v += __shfl_down_sync(0xffffffffu, v, o);
        if (l == 0) dsum[batch][w] = v;
    }
    BBAR();
    if (L == 0 && bv) {
        float  Gv = gall[batch][sl];
        int    ev = eall[batch][sl >> 3];
        double lv = (double)logf(Gv) + (double)ev * 0.6931471805599453
                  + dsum[batch][0] + dsum[batch][1];
        out[bb] = (float)(-lv / (double)nt);
    }
}

extern "C" void kernel_launch(void* const* d_in, const int* in_sizes, int n_in,
                              void* d_out, int out_size) {
    const float* x       = (const float*)d_in[0];
    const int*   seqs    = (const int*)  d_in[1];
    const int*   seqlens = (const int*)  d_in[2];
    float*       out     = (float*)d_out;

    const int nb = in_sizes[2];
    const int ns = in_sizes[1] / nb;
    const int nt = in_sizes[0] / (nb * 5);

    ctc_fwd<<<(nb + 1) / 2, TPB>>>(x, seqs, seqlens, out, nt, nb, ns);
}

// round 13
// speedup vs baseline: 1.5971x; 1.5971x over previous
#include <cuda_runtime.h>

// CTC forward scan, linear domain, x4-factored:
//   G_j(t+1) = W_t[s_j]*G_{j-1}(t) + G_j(t),  W_t[s] = exp(x[t,s]-x[t,4])
//   fwd[j] = log(G) + e*ln2 + sum_t x4
//
// R12: single warp per batch, ZERO barriers (R7 frame — R9's two-warp
// variant regressed: 8-step cross-warp barriers cost more than they saved).
//  - 32 lanes x PB positions; PB templated {8,12,16} chosen by seqlen.
//  - Trapezoid KB=8: lane holds KB-wide left overlap + PB owned; 8 steps
//    between shfl exchanges (8 value shfl + 1 packed (e,ex,hasmass) shfl).
//  - W pair-table (16 rows of (W[a],W[b]) float2, PSTR=33): written and
//    read by the same warp; one __syncwarp per 32-step chunk.
//  - Ladder LDS use per-chunk hoisted row pointers advanced += KB per
//    region => immediate offsets, no per-load address IMADs.
//  - Scaling: per-lane pow2 exponent, pre-renorm halo, common-scale mixing
//    with all factors <= 1 (no overflow; underflow flush correct).
//  - 2 independent warps (batches) per 64-thread CTA, grid=128 -> 1 CTA/SM.

#define XCH  32
#define KB   8
#define PSTR 33
#define NBAT 2
#define TPB  (32 * NBAT)

__device__ __forceinline__ float exp2i_le(int d) {
    int b = d + 127;
    b = b < 0 ? 0 : (b > 254 ? 254 : b);
    return __int_as_float(b << 23);
}

template<int PB>
__device__ __forceinline__ void scan_batch(
    const float* __restrict__ x, const int* __restrict__ seqs,
    int sl, int bb, int nt, int nb, int ns,
    float* __restrict__ out,
    float2* __restrict__ shP,    // [2][16*PSTR]
    float*  __restrict__ gall,   // [32*PB]
    int*    __restrict__ eall)   // [32]
{
    constexpr int NU = PB + KB - 1;       // updates per step (odd)
    constexpr int NP = (NU + 1) / 2;      // pair rows (last single, padded)
    const int l    = threadIdx.x & 31;
    const int jmin = l * PB;

    // move indices: update i writes G[i+1] (position jmin+i+1-KB), uses
    // seqs[jmin+i-KB]
    int s[NU + 1];
    #pragma unroll
    for (int k = 0; k < NU; ++k) {
        int q = jmin + k - KB;
        s[k] = (q >= 0 && q < ns) ? seqs[(long long)bb * ns + q] : 0;
    }
    s[NU] = s[NU - 1];
    int pq[NP];
    #pragma unroll
    for (int q = 0; q < NP; ++q)
        pq[q] = (s[2 * q] * 4 + s[2 * q + 1]) * PSTR;

    float G[KB + PB];
    #pragma unroll
    for (int i = 0; i < KB + PB; ++i) G[i] = 0.0f;
    if (l == 0) G[KB] = 1.0f;             // position 0: fwd=0 -> G=1
    int e = 0;

    float a0 = 0.f, a1 = 0.f, a2 = 0.f, a3 = 0.f, a4 = 0.f;
    double x4s = 0.0;

    auto prefetch = [&](int c) {          // LDG only (regs), one tau per lane
        int tt = c * XCH + l;
        if (tt < nt) {
            const float* xp = x + ((long long)tt * nb + bb) * 5;
            a0 = xp[0]; a1 = xp[1]; a2 = xp[2]; a3 = xp[3]; a4 = xp[4];
        } else {
            a0 = a1 = a2 = a3 = -1e9f;    // exp -> 0: steps past nt freeze G
            a4 = 0.f;
        }
    };
    auto convert = [&](int c) {           // expf + 16 STS.64 pair rows
        float w[4];
        w[0] = __expf(a0 - a4); w[1] = __expf(a1 - a4);
        w[2] = __expf(a2 - a4); w[3] = __expf(a3 - a4);
        float2* row = shP + (c & 1) * (16 * PSTR) + l;
        #pragma unroll
        for (int aa = 0; aa < 4; ++aa)
            #pragma unroll
            for (int bq = 0; bq < 4; ++bq)
                row[(aa * 4 + bq) * PSTR] = make_float2(w[aa], w[bq]);
        if (c * XCH + l < nt) x4s += (double)a4;
    };

    prefetch(0); convert(0); prefetch(1);
    __syncwarp();

    const int NC = (nt + XCH - 1) / XCH;
    for (int c = 0; c < NC; ++c) {
        // hoist pair-row pointers: ladder LDS get immediate offsets only
        const float2* rp[NP];
        {
            const float2* cbb = shP + (c & 1) * (16 * PSTR);
            #pragma unroll
            for (int q = 0; q < NP; ++q) rp[q] = cbb + pq[q];
        }
        #pragma unroll 1
        for (int r = 0; r < XCH / KB; ++r) {
            // ---- exchange (shfl halo, common-scale mixing) ----
            float mx = G[KB];
            #pragma unroll
            for (int i = KB + 1; i < KB + PB; ++i) mx = fmaxf(mx, G[i]);
            int ex = (__float_as_int(mx) >> 23) - 127;
            int hm = (mx > 0.0f) ? 1 : 0;
            int pack  = (e << 9) | ((ex + 128) << 1) | hm;
            int packL = __shfl_up_sync(0xffffffffu, pack, 1);
            float h[KB];
            #pragma unroll
            for (int i = 0; i < KB; ++i)       // left lane's top KB owned
                h[i] = __shfl_up_sync(0xffffffffu, G[PB + i], 1);
            int hL  = (l == 0) ? 0 : (packL & 1);
            int exL = ((packL >> 1) & 255) - 128;
            int eL  = packL >> 9;              // arithmetic shift: sign kept
            const int NEG = -(1 << 29);
            int EO = hm ? (e + ex)   : NEG;
            int EL = hL ? (eL + exL) : NEG;
            int cc = EO > EL ? EO : EL;
            if (cc == NEG) cc = 0;
            float rs = exp2i_le(e - cc);       // <= 2^-ex -> post-mix <= 2
            float rl = hL ? exp2i_le(eL - cc) : 0.0f;
            #pragma unroll
            for (int i = 0; i < KB; ++i) G[i] = h[i] * rl;
            #pragma unroll
            for (int i = KB; i < KB + PB; ++i) G[i] *= rs;
            e = cc;

            // ---- ladder: KB steps, per-step loads (ptxas pipelines) ----
            #pragma unroll
            for (int k = 0; k < KB; ++k) {
                float2 W[NP];
                #pragma unroll
                for (int q = 0; q < NP; ++q) W[q] = rp[q][k];
                // in-place, strictly descending targets (pre-step reads)
                G[NU] = fmaf(W[NP - 1].x, G[NU - 1], G[NU]);
                #pragma unroll
                for (int q = NP - 2; q >= 0; --q) {
                    G[2*q + 2] = fmaf(W[q].y, G[2*q + 1], G[2*q + 2]);
                    G[2*q + 1] = fmaf(W[q].x, G[2*q],     G[2*q + 1]);
                }
            }
            #pragma unroll
            for (int q = 0; q < NP; ++q) rp[q] += KB;
        }
        convert(c + 1);      // regs from prefetch(c+1)
        __syncwarp();        // cross-lane table visibility
        prefetch(c + 2);
    }

    // ---- epilogue ----
    #pragma unroll
    for (int i = 0; i < PB; ++i) gall[jmin + i] = G[KB + i];
    eall[l] = e;
    double v = x4s;
    #pragma unroll
    for (int o = 16; o; o >>= 1)
        v += __shfl_down_sync(0xffffffffu, v, o);
    __syncwarp();
    if (l == 0) {
        float  Gv = gall[sl];
        int    ev = eall[sl / PB];
        double lv = (double)logf(Gv) + (double)ev * 0.6931471805599453 + v;
        out[bb] = (float)(-lv / (double)nt);
    }
}

__global__ __launch_bounds__(TPB)
void ctc_fwd(const float* __restrict__ x,
             const int*   __restrict__ seqs,
             const int*   __restrict__ seqlens,
             float*       __restrict__ out,
             int nt, int nb, int ns)
{
    __shared__ float2 shP [NBAT][2 * 16 * PSTR];
    __shared__ float  gall[NBAT][512];
    __shared__ int    eall[NBAT][32];

    const int w  = threadIdx.x >> 5;
    const int bb = blockIdx.x * NBAT + w;
    if (bb >= nb) return;                  // warp-uniform exit
    const int sl = seqlens[bb];

    if (sl < 8 * 32)
        scan_batch<8>(x, seqs, sl, bb, nt, nb, ns, out,
                      shP[w], gall[w], eall[w]);
    else if (sl < 12 * 32)
        scan_batch<12>(x, seqs, sl, bb, nt, nb, ns, out,
                       shP[w], gall[w], eall[w]);
    else
        scan_batch<16>(x, seqs, sl, bb, nt, nb, ns, out,
                       shP[w], gall[w], eall[w]);
}

extern "C" void kernel_launch(void* const* d_in, const int* in_sizes, int n_in,
                              void* d_out, int out_size) {
    const float* x       = (const float*)d_in[0];
    const int*   seqs    = (const int*)  d_in[1];
    const int*   seqlens = (const int*)  d_in[2];
    float*       out     = (float*)d_out;

    const int nb = in_sizes[2];
    const int ns = in_sizes[1] / nb;
    const int nt = in_sizes[0] / (nb * 5);

    ctc_fwd<<<(nb + NBAT - 1) / NBAT, TPB>>>(x, seqs, seqlens, out, nt, nb, ns);
}